// round 11
// baseline (speedup 1.0000x reference)
#include <cuda_runtime.h>
#include <math.h>

// Problem constants (fixed by the dataset)
#define kN    20000
#define kE    320000
#define kSED  768
#define kHC   512     // heads * channels layer 1
#define kH    4
#define kHID  128
#define kF    128     // layer-2 output channels

#define NEG_INF (-3.402823466e38f)
#define TF32_MASK 0xFFFFE000u

// ---------------- scratch (no allocation allowed) ----------------
__device__ float g_h1[kN * kHC];        // layer-1 pre-bias features (messages)
__device__ float g_h2[kN * kF];         // layer-2 pre-bias features
__device__ float g_c1[kHC];             // sent @ W1[768:1536]
__device__ float g_es1[kN * kH];
__device__ float g_ed1[kN * kH];
__device__ float g_es2[kN];
__device__ float g_ed2[kN];
__device__ float g_m1[kN * kH];
__device__ float g_rs1[kN * kH];
__device__ float g_m2[kN];
__device__ float g_rs2[kN];
__device__ int   g_deg[kN];
__device__ int   g_cursor[kN];
__device__ int   g_rowptr[kN + 1];
__device__ int   g_tscan[kN];
__device__ int   g_bsum[32];
__device__ int   g_boff[32];
__device__ int   g_srcs[kE];            // src node ids sorted by dst

// pre-split tf32 hi/lo operand arrays
__device__ float g_xh[kN * kSED];
__device__ float g_xl[kN * kSED];
__device__ float g_w1h[kSED * kHC];
__device__ float g_w1l[kSED * kHC];
__device__ float g_h1h[kN * kHC];       // split of ELU(agg1 output)
__device__ float g_h1l[kN * kHC];
__device__ float g_w2h[kHC * kF];
__device__ float g_w2l[kHC * kF];

// ---------------- CSR build ----------------
__global__ void k_zero_deg() {
    int i = blockIdx.x * blockDim.x + threadIdx.x;
    if (i < kN) g_deg[i] = 0;
}

__global__ void k_hist(const int* __restrict__ ei) {
    int e = blockIdx.x * blockDim.x + threadIdx.x;
    if (e < kE) atomicAdd(&g_deg[ei[kE + e]], 1);
}

__global__ void k_scan1() {
    __shared__ int sm[1024];
    int i = blockIdx.x * 1024 + threadIdx.x;
    int v = (i < kN) ? g_deg[i] : 0;
    sm[threadIdx.x] = v;
    __syncthreads();
    for (int off = 1; off < 1024; off <<= 1) {
        int t = (threadIdx.x >= off) ? sm[threadIdx.x - off] : 0;
        __syncthreads();
        sm[threadIdx.x] += t;
        __syncthreads();
    }
    if (i < kN) g_tscan[i] = sm[threadIdx.x];
    if (threadIdx.x == 1023) g_bsum[blockIdx.x] = sm[1023];
}

__global__ void k_scan2(int nb) {
    if (threadIdx.x == 0) {
        int run = 0;
        for (int b = 0; b < nb; b++) { g_boff[b] = run; run += g_bsum[b]; }
    }
}

__global__ void k_scan3() {
    int i = blockIdx.x * blockDim.x + threadIdx.x;
    if (i < kN) {
        int incl = g_tscan[i] + g_boff[i >> 10];
        g_rowptr[i + 1] = incl;
        g_cursor[i]     = incl - g_deg[i];
        if (i == 0) g_rowptr[0] = 0;
    }
}

__global__ void k_scatter(const int* __restrict__ ei) {
    int e = blockIdx.x * blockDim.x + threadIdx.x;
    if (e < kE) {
        int d = ei[kE + e];
        int pos = atomicAdd(&g_cursor[d], 1);
        g_srcs[pos] = ei[e];
    }
}

// ---------------- tf32 hi/lo pre-split (mask truncation, no cvt) ----------------
__device__ __forceinline__ float tf32_hi(float x) {
    return __uint_as_float(__float_as_uint(x) & TF32_MASK);
}

__global__ void k_split4(const float4* __restrict__ in, float4* __restrict__ hi,
                         float4* __restrict__ lo, int n4) {
    int i = blockIdx.x * blockDim.x + threadIdx.x;
    if (i >= n4) return;
    float4 v = in[i];
    float4 h = make_float4(tf32_hi(v.x), tf32_hi(v.y), tf32_hi(v.z), tf32_hi(v.w));
    hi[i] = h;
    lo[i] = make_float4(v.x - h.x, v.y - h.y, v.z - h.z, v.w - h.w);
}

// ---------------- constant column bias: c1 = sent @ W1[768:1536] ----------------
__global__ void k_c1(const float* __restrict__ sent, const float* __restrict__ W1) {
    int j = blockIdx.x * blockDim.x + threadIdx.x;   // 0..511
    if (j >= kHC) return;
    float acc = 0.f;
    for (int k = 0; k < kSED; k++)
        acc += sent[k] * W1[(kSED + k) * kHC + j];
    g_c1[j] = acc;
}

// ---------------- tf32 tensor-core GEMM, pre-split operands, double-buffered ----------------
// C[M,N] = A[M,K] @ B[K,N] (+ colbias), A/B given as hi/lo pairs.
// Block 128x128, k-tile 16, 256 thr = 8 warps of 64x32. D = Ah*Bh + Ah*Bl + Al*Bh.
#define GBM 128
#define GBN 128
#define GBK 16
#define APAD 20
#define BPAD 136
#define OFF_AH 0
#define OFF_AL 2560           // 128*20
#define OFF_BH 5120
#define OFF_BL 7296           // 5120 + 16*136
#define BUF_FLOATS 9472       // 7296 + 16*136

__device__ __forceinline__ void mma_tf32(float* c,
    unsigned a0, unsigned a1, unsigned a2, unsigned a3,
    unsigned b0, unsigned b1)
{
    asm volatile(
        "mma.sync.aligned.m16n8k8.row.col.f32.tf32.tf32.f32 "
        "{%0,%1,%2,%3},{%4,%5,%6,%7},{%8,%9},{%0,%1,%2,%3};"
        : "+f"(c[0]), "+f"(c[1]), "+f"(c[2]), "+f"(c[3])
        : "r"(a0), "r"(a1), "r"(a2), "r"(a3), "r"(b0), "r"(b1));
}

__device__ __forceinline__ void stash_tile(
    float* buf, int aM0, int aM1, int aK, int bK0, int bK1, int bN,
    float4 va0h, float4 va0l, float4 va1h, float4 va1l,
    float4 vb0h, float4 vb0l, float4 vb1h, float4 vb1l)
{
    *(float4*)&buf[OFF_AH + aM0 * APAD + aK] = va0h;
    *(float4*)&buf[OFF_AL + aM0 * APAD + aK] = va0l;
    *(float4*)&buf[OFF_AH + aM1 * APAD + aK] = va1h;
    *(float4*)&buf[OFF_AL + aM1 * APAD + aK] = va1l;
    *(float4*)&buf[OFF_BH + bK0 * BPAD + bN] = vb0h;
    *(float4*)&buf[OFF_BL + bK0 * BPAD + bN] = vb0l;
    *(float4*)&buf[OFF_BH + bK1 * BPAD + bN] = vb1h;
    *(float4*)&buf[OFF_BL + bK1 * BPAD + bN] = vb1l;
}

__global__ void __launch_bounds__(256) k_mma_gemm(
    const float* __restrict__ Ah, const float* __restrict__ Al,
    const float* __restrict__ Bh, const float* __restrict__ Bl,
    float* __restrict__ C,
    int M, int N, int K, const float* __restrict__ colbias)
{
    extern __shared__ float smbuf[];

    int tid  = threadIdx.x;
    int wid  = tid >> 5, lane = tid & 31;
    int g    = lane >> 2, tg = lane & 3;
    int warpM = (wid >> 2) * 64;   // 0 or 64
    int warpN = (wid & 3) * 32;    // 0,32,64,96
    int rowBase = blockIdx.y * GBM;
    int colBase = blockIdx.x * GBN;

    int aM0 = tid >> 2,          aK = (tid & 3) << 2;
    int aM1 = aM0 + 64;
    int bK0 = tid >> 5,          bN = (tid & 31) << 2;
    int bK1 = bK0 + 8;

    float acc[4][4][4];
    #pragma unroll
    for (int i = 0; i < 4; i++)
        #pragma unroll
        for (int j = 0; j < 4; j++)
            #pragma unroll
            for (int r = 0; r < 4; r++) acc[i][j][r] = 0.f;

    const float4 z4 = make_float4(0.f, 0.f, 0.f, 0.f);
    int T = K / GBK;

    // load + stash tile 0
    {
        int gm0 = rowBase + aM0, gm1 = rowBase + aM1;
        long a0off = (long)gm0 * K + aK;
        long a1off = (long)gm1 * K + aK;
        float4 va0h = (gm0 < M) ? *(const float4*)&Ah[a0off] : z4;
        float4 va0l = (gm0 < M) ? *(const float4*)&Al[a0off] : z4;
        float4 va1h = (gm1 < M) ? *(const float4*)&Ah[a1off] : z4;
        float4 va1l = (gm1 < M) ? *(const float4*)&Al[a1off] : z4;
        long b0off = (long)bK0 * N + colBase + bN;
        long b1off = (long)bK1 * N + colBase + bN;
        float4 vb0h = *(const float4*)&Bh[b0off];
        float4 vb0l = *(const float4*)&Bl[b0off];
        float4 vb1h = *(const float4*)&Bh[b1off];
        float4 vb1l = *(const float4*)&Bl[b1off];
        stash_tile(smbuf, aM0, aM1, aK, bK0, bK1, bN,
                   va0h, va0l, va1h, va1l, vb0h, vb0l, vb1h, vb1l);
    }
    __syncthreads();

    for (int t = 0; t < T; t++) {
        float* cur = smbuf + (t & 1) * BUF_FLOATS;
        float* AhF = cur + OFF_AH;
        float* AlF = cur + OFF_AL;
        float* BhF = cur + OFF_BH;
        float* BlF = cur + OFF_BL;

        float4 pa0h, pa0l, pa1h, pa1l, pb0h, pb0l, pb1h, pb1l;
        bool more = (t + 1 < T);
        if (more) {
            int k0 = (t + 1) * GBK;
            int gm0 = rowBase + aM0, gm1 = rowBase + aM1;
            long a0off = (long)gm0 * K + k0 + aK;
            long a1off = (long)gm1 * K + k0 + aK;
            pa0h = (gm0 < M) ? *(const float4*)&Ah[a0off] : z4;
            pa0l = (gm0 < M) ? *(const float4*)&Al[a0off] : z4;
            pa1h = (gm1 < M) ? *(const float4*)&Ah[a1off] : z4;
            pa1l = (gm1 < M) ? *(const float4*)&Al[a1off] : z4;
            long b0off = (long)(k0 + bK0) * N + colBase + bN;
            long b1off = (long)(k0 + bK1) * N + colBase + bN;
            pb0h = *(const float4*)&Bh[b0off];
            pb0l = *(const float4*)&Bl[b0off];
            pb1h = *(const float4*)&Bh[b1off];
            pb1l = *(const float4*)&Bl[b1off];
        }

        #pragma unroll
        for (int ks = 0; ks < GBK; ks += 8) {
            unsigned ah[4][4], al[4][4];
            #pragma unroll
            for (int i = 0; i < 4; i++) {
                int rm = warpM + i * 16;
                ah[i][0] = __float_as_uint(AhF[(rm + g    ) * APAD + ks + tg    ]);
                ah[i][1] = __float_as_uint(AhF[(rm + g + 8) * APAD + ks + tg    ]);
                ah[i][2] = __float_as_uint(AhF[(rm + g    ) * APAD + ks + tg + 4]);
                ah[i][3] = __float_as_uint(AhF[(rm + g + 8) * APAD + ks + tg + 4]);
                al[i][0] = __float_as_uint(AlF[(rm + g    ) * APAD + ks + tg    ]);
                al[i][1] = __float_as_uint(AlF[(rm + g + 8) * APAD + ks + tg    ]);
                al[i][2] = __float_as_uint(AlF[(rm + g    ) * APAD + ks + tg + 4]);
                al[i][3] = __float_as_uint(AlF[(rm + g + 8) * APAD + ks + tg + 4]);
            }
            unsigned bh[4][2], bl[4][2];
            #pragma unroll
            for (int j = 0; j < 4; j++) {
                int cn = warpN + j * 8;
                bh[j][0] = __float_as_uint(BhF[(ks + tg    ) * BPAD + cn + g]);
                bh[j][1] = __float_as_uint(BhF[(ks + tg + 4) * BPAD + cn + g]);
                bl[j][0] = __float_as_uint(BlF[(ks + tg    ) * BPAD + cn + g]);
                bl[j][1] = __float_as_uint(BlF[(ks + tg + 4) * BPAD + cn + g]);
            }
            #pragma unroll
            for (int i = 0; i < 4; i++)
                #pragma unroll
                for (int j = 0; j < 4; j++) {
                    mma_tf32(acc[i][j], ah[i][0], ah[i][1], ah[i][2], ah[i][3], bh[j][0], bh[j][1]);
                    mma_tf32(acc[i][j], ah[i][0], ah[i][1], ah[i][2], ah[i][3], bl[j][0], bl[j][1]);
                    mma_tf32(acc[i][j], al[i][0], al[i][1], al[i][2], al[i][3], bh[j][0], bh[j][1]);
                }
        }

        if (more) {
            float* nxt = smbuf + ((t + 1) & 1) * BUF_FLOATS;
            stash_tile(nxt, aM0, aM1, aK, bK0, bK1, bN,
                       pa0h, pa0l, pa1h, pa1l, pb0h, pb0l, pb1h, pb1l);
            __syncthreads();
        }
    }

    // epilogue
    #pragma unroll
    for (int i = 0; i < 4; i++) {
        int r0 = rowBase + warpM + i * 16 + g;
        int r1 = r0 + 8;
        #pragma unroll
        for (int j = 0; j < 4; j++) {
            int c = colBase + warpN + j * 8 + tg * 2;
            float2 v0 = make_float2(acc[i][j][0], acc[i][j][1]);
            float2 v1 = make_float2(acc[i][j][2], acc[i][j][3]);
            if (colbias) {
                float cb0 = colbias[c], cb1 = colbias[c + 1];
                v0.x += cb0; v0.y += cb1;
                v1.x += cb0; v1.y += cb1;
            }
            if (r0 < M) *(float2*)&C[(long)r0 * N + c] = v0;
            if (r1 < M) *(float2*)&C[(long)r1 * N + c] = v1;
        }
    }
}

// ---------------- attention scalar dots ----------------
__global__ void k_dots1(const float* __restrict__ a_src, const float* __restrict__ a_dst) {
    int gw = (blockIdx.x * blockDim.x + threadIdx.x) >> 5;
    int lane = threadIdx.x & 31;
    if (gw >= kN * kH) return;
    int n = gw >> 2, h = gw & 3;
    const float* row = g_h1 + (long)n * kHC + h * kHID;
    const float* as = a_src + h * kHID;
    const float* ad = a_dst + h * kHID;
    float s1 = 0.f, s2 = 0.f;
    #pragma unroll
    for (int c = lane; c < kHID; c += 32) {
        float v = row[c];
        s1 += v * as[c];
        s2 += v * ad[c];
    }
    #pragma unroll
    for (int o = 16; o; o >>= 1) {
        s1 += __shfl_xor_sync(0xffffffffu, s1, o);
        s2 += __shfl_xor_sync(0xffffffffu, s2, o);
    }
    if (lane == 0) { g_es1[gw] = s1; g_ed1[gw] = s2; }
}

__global__ void k_dots2(const float* __restrict__ a_src, const float* __restrict__ a_dst) {
    int gw = (blockIdx.x * blockDim.x + threadIdx.x) >> 5;
    int lane = threadIdx.x & 31;
    if (gw >= kN) return;
    const float* row = g_h2 + (long)gw * kF;
    float s1 = 0.f, s2 = 0.f;
    #pragma unroll
    for (int c = lane; c < kF; c += 32) {
        float v = row[c];
        s1 += v * a_src[c];
        s2 += v * a_dst[c];
    }
    #pragma unroll
    for (int o = 16; o; o >>= 1) {
        s1 += __shfl_xor_sync(0xffffffffu, s1, o);
        s2 += __shfl_xor_sync(0xffffffffu, s2, o);
    }
    if (lane == 0) { g_es2[gw] = s1; g_ed2[gw] = s2; }
}

// ---------------- warp-per-node softmax stats ----------------
__global__ void k_stats1() {
    int gw = (blockIdx.x * blockDim.x + threadIdx.x) >> 5;   // node
    int lane = threadIdx.x & 31;
    if (gw >= kN) return;
    int beg = g_rowptr[gw], end = g_rowptr[gw + 1];
    float4 ed = *(const float4*)&g_ed1[gw * 4];

    float m0 = NEG_INF, m1 = NEG_INF, m2 = NEG_INF, m3 = NEG_INF;
    for (int j = beg + lane; j < end; j += 32) {
        int s = g_srcs[j];
        float4 es = *(const float4*)&g_es1[s * 4];
        float e0 = es.x + ed.x; e0 = e0 > 0.f ? e0 : 0.2f * e0;
        float e1 = es.y + ed.y; e1 = e1 > 0.f ? e1 : 0.2f * e1;
        float e2 = es.z + ed.z; e2 = e2 > 0.f ? e2 : 0.2f * e2;
        float e3 = es.w + ed.w; e3 = e3 > 0.f ? e3 : 0.2f * e3;
        m0 = fmaxf(m0, e0); m1 = fmaxf(m1, e1);
        m2 = fmaxf(m2, e2); m3 = fmaxf(m3, e3);
    }
    #pragma unroll
    for (int o = 16; o; o >>= 1) {
        m0 = fmaxf(m0, __shfl_xor_sync(0xffffffffu, m0, o));
        m1 = fmaxf(m1, __shfl_xor_sync(0xffffffffu, m1, o));
        m2 = fmaxf(m2, __shfl_xor_sync(0xffffffffu, m2, o));
        m3 = fmaxf(m3, __shfl_xor_sync(0xffffffffu, m3, o));
    }
    float s0 = 0.f, s1 = 0.f, s2 = 0.f, s3 = 0.f;
    for (int j = beg + lane; j < end; j += 32) {
        int s = g_srcs[j];
        float4 es = *(const float4*)&g_es1[s * 4];
        float e0 = es.x + ed.x; e0 = e0 > 0.f ? e0 : 0.2f * e0;
        float e1 = es.y + ed.y; e1 = e1 > 0.f ? e1 : 0.2f * e1;
        float e2 = es.z + ed.z; e2 = e2 > 0.f ? e2 : 0.2f * e2;
        float e3 = es.w + ed.w; e3 = e3 > 0.f ? e3 : 0.2f * e3;
        s0 += __expf(e0 - m0); s1 += __expf(e1 - m1);
        s2 += __expf(e2 - m2); s3 += __expf(e3 - m3);
    }
    #pragma unroll
    for (int o = 16; o; o >>= 1) {
        s0 += __shfl_xor_sync(0xffffffffu, s0, o);
        s1 += __shfl_xor_sync(0xffffffffu, s1, o);
        s2 += __shfl_xor_sync(0xffffffffu, s2, o);
        s3 += __shfl_xor_sync(0xffffffffu, s3, o);
    }
    if (lane == 0) {
        *(float4*)&g_m1[gw * 4]  = make_float4(m0, m1, m2, m3);
        *(float4*)&g_rs1[gw * 4] = make_float4(1.f / (s0 + 1e-16f), 1.f / (s1 + 1e-16f),
                                               1.f / (s2 + 1e-16f), 1.f / (s3 + 1e-16f));
    }
}

__global__ void k_stats2() {
    int gw = (blockIdx.x * blockDim.x + threadIdx.x) >> 5;
    int lane = threadIdx.x & 31;
    if (gw >= kN) return;
    int beg = g_rowptr[gw], end = g_rowptr[gw + 1];
    float ed = g_ed2[gw];
    float m = NEG_INF;
    for (int j = beg + lane; j < end; j += 32) {
        float e = g_es2[g_srcs[j]] + ed;
        e = e > 0.f ? e : 0.2f * e;
        m = fmaxf(m, e);
    }
    #pragma unroll
    for (int o = 16; o; o >>= 1) m = fmaxf(m, __shfl_xor_sync(0xffffffffu, m, o));
    float s = 0.f;
    for (int j = beg + lane; j < end; j += 32) {
        float e = g_es2[g_srcs[j]] + ed;
        e = e > 0.f ? e : 0.2f * e;
        s += __expf(e - m);
    }
    #pragma unroll
    for (int o = 16; o; o >>= 1) s += __shfl_xor_sync(0xffffffffu, s, o);
    if (lane == 0) { g_m2[gw] = m; g_rs2[gw] = 1.f / (s + 1e-16f); }
}

// ---------------- layer-1 aggregation: gather only, +b1, ELU, split-write ----------------
__global__ void __launch_bounds__(512) k_agg1(const float* __restrict__ b1) {
    __shared__ float msm[4], rssm[4], edsm[4];
    __shared__ float alpha_sm[128 * 4];
    __shared__ int   src_sm[128];

    int v = blockIdx.x;
    int tid = threadIdx.x;
    int beg = g_rowptr[v], end = g_rowptr[v + 1];
    int h = tid >> 7;

    if (tid < 4) {
        msm[tid]  = g_m1[v * 4 + tid];
        rssm[tid] = g_rs1[v * 4 + tid];
        edsm[tid] = g_ed1[v * 4 + tid];
    }
    __syncthreads();

    float acc0 = 0.f, acc1 = 0.f, acc2 = 0.f, acc3 = 0.f;
    for (int cb = beg; cb < end; cb += 128) {
        int cn = min(128, end - cb);
        for (int idx = tid; idx < cn * 4; idx += 512) {
            int j = idx >> 2, hh = idx & 3;
            int s = g_srcs[cb + j];
            float e = g_es1[s * 4 + hh] + edsm[hh];
            e = e > 0.f ? e : 0.2f * e;
            alpha_sm[(j << 2) + hh] = __expf(e - msm[hh]) * rssm[hh];
            if (hh == 0) src_sm[j] = s;
        }
        __syncthreads();
        int j = 0;
        for (; j + 4 <= cn; j += 4) {
            float a0 = alpha_sm[(j << 2) + h];
            float a1 = alpha_sm[((j + 1) << 2) + h];
            float a2 = alpha_sm[((j + 2) << 2) + h];
            float a3 = alpha_sm[((j + 3) << 2) + h];
            int s0 = src_sm[j], s1 = src_sm[j + 1], s2 = src_sm[j + 2], s3 = src_sm[j + 3];
            acc0 += a0 * g_h1[(long)s0 * kHC + tid];
            acc1 += a1 * g_h1[(long)s1 * kHC + tid];
            acc2 += a2 * g_h1[(long)s2 * kHC + tid];
            acc3 += a3 * g_h1[(long)s3 * kHC + tid];
        }
        for (; j < cn; j++)
            acc0 += alpha_sm[(j << 2) + h] * g_h1[(long)src_sm[j] * kHC + tid];
        __syncthreads();
    }
    float o = acc0 + acc1 + acc2 + acc3 + b1[tid];
    o = o > 0.f ? o : (__expf(o) - 1.f);   // ELU(alpha=1)
    float hi = tf32_hi(o);
    g_h1h[(long)v * kHC + tid] = hi;
    g_h1l[(long)v * kHC + tid] = o - hi;
}

// ---------------- layer-2 aggregation (single head), +b2, write out ----------------
__global__ void __launch_bounds__(128) k_agg2(const float* __restrict__ b2, float* __restrict__ out) {
    __shared__ float alpha_sm[256];
    __shared__ int   src_sm[256];

    int v = blockIdx.x;
    int tid = threadIdx.x;
    int beg = g_rowptr[v], end = g_rowptr[v + 1];
    float edv = g_ed2[v];
    float m = g_m2[v];
    float rs = g_rs2[v];

    float acc0 = 0.f, acc1 = 0.f, acc2 = 0.f, acc3 = 0.f;
    for (int cb = beg; cb < end; cb += 256) {
        int cn = min(256, end - cb);
        for (int idx = tid; idx < cn; idx += 128) {
            int s = g_srcs[cb + idx];
            float e = g_es2[s] + edv;
            e = e > 0.f ? e : 0.2f * e;
            alpha_sm[idx] = __expf(e - m) * rs;
            src_sm[idx] = s;
        }
        __syncthreads();
        int j = 0;
        for (; j + 4 <= cn; j += 4) {
            float a0 = alpha_sm[j], a1 = alpha_sm[j + 1], a2 = alpha_sm[j + 2], a3 = alpha_sm[j + 3];
            int s0 = src_sm[j], s1 = src_sm[j + 1], s2 = src_sm[j + 2], s3 = src_sm[j + 3];
            acc0 += a0 * g_h2[(long)s0 * kF + tid];
            acc1 += a1 * g_h2[(long)s1 * kF + tid];
            acc2 += a2 * g_h2[(long)s2 * kF + tid];
            acc3 += a3 * g_h2[(long)s3 * kF + tid];
        }
        for (; j < cn; j++)
            acc0 += alpha_sm[j] * g_h2[(long)src_sm[j] * kF + tid];
        __syncthreads();
    }
    out[(long)v * kF + tid] = acc0 + acc1 + acc2 + acc3 + b2[tid];
}

// ---------------- launch ----------------
extern "C" void kernel_launch(void* const* d_in, const int* in_sizes, int n_in,
                              void* d_out, int out_size) {
    const float* x    = (const float*)d_in[0];
    const int*   ei   = (const int*)d_in[1];
    const float* sent = (const float*)d_in[2];
    const float* W1   = (const float*)d_in[3];
    const float* a1s  = (const float*)d_in[4];
    const float* a1d  = (const float*)d_in[5];
    const float* b1   = (const float*)d_in[6];
    const float* W2   = (const float*)d_in[7];
    const float* a2s  = (const float*)d_in[8];
    const float* a2d  = (const float*)d_in[9];
    const float* b2   = (const float*)d_in[10];
    float* out = (float*)d_out;

    const int dynsmem = BUF_FLOATS * 2 * (int)sizeof(float);   // 75776 B
    cudaFuncSetAttribute(k_mma_gemm, cudaFuncAttributeMaxDynamicSharedMemorySize, dynsmem);

    // symbol addresses
    float *xh, *xl, *w1h, *w1l, *h1h, *h1l, *w2h, *w2l, *c1p, *h1p, *h2p;
    cudaGetSymbolAddress((void**)&xh,  g_xh);
    cudaGetSymbolAddress((void**)&xl,  g_xl);
    cudaGetSymbolAddress((void**)&w1h, g_w1h);
    cudaGetSymbolAddress((void**)&w1l, g_w1l);
    cudaGetSymbolAddress((void**)&h1h, g_h1h);
    cudaGetSymbolAddress((void**)&h1l, g_h1l);
    cudaGetSymbolAddress((void**)&w2h, g_w2h);
    cudaGetSymbolAddress((void**)&w2l, g_w2l);
    cudaGetSymbolAddress((void**)&c1p, g_c1);
    cudaGetSymbolAddress((void**)&h1p, g_h1);
    cudaGetSymbolAddress((void**)&h2p, g_h2);

    // pre-split inputs (one-time per call, memory-bound)
    {
        int n4 = kN * kSED / 4;
        k_split4<<<(n4 + 255) / 256, 256>>>((const float4*)x, (float4*)xh, (float4*)xl, n4);
    }
    {
        int n4 = kSED * kHC / 4;   // only rows [0:768) of W1 feed the GEMM
        k_split4<<<(n4 + 255) / 256, 256>>>((const float4*)W1, (float4*)w1h, (float4*)w1l, n4);
    }
    {
        int n4 = kHC * kF / 4;
        k_split4<<<(n4 + 255) / 256, 256>>>((const float4*)W2, (float4*)w2h, (float4*)w2l, n4);
    }

    // CSR build (shared by both layers)
    k_zero_deg<<<(kN + 255) / 256, 256>>>();
    k_hist<<<(kE + 255) / 256, 256>>>(ei);
    k_scan1<<<(kN + 1023) / 1024, 1024>>>();
    k_scan2<<<1, 32>>>((kN + 1023) / 1024);
    k_scan3<<<(kN + 255) / 256, 256>>>();
    k_scatter<<<(kE + 255) / 256, 256>>>(ei);

    // layer 1
    k_c1<<<2, 256>>>(sent, W1);
    {
        dim3 g(kHC / 128, (kN + 127) / 128);
        k_mma_gemm<<<g, 256, dynsmem>>>(xh, xl, w1h, w1l, h1p, kN, kHC, kSED, c1p);
    }
    k_dots1<<<(kN * kH * 32 + 255) / 256, 256>>>(a1s, a1d);
    k_stats1<<<(kN * 32 + 255) / 256, 256>>>();
    k_agg1<<<kN, 512>>>(b1);

    // layer 2
    {
        dim3 g(kF / 128, (kN + 127) / 128);
        k_mma_gemm<<<g, 256, dynsmem>>>(h1h, h1l, w2h, w2l, h2p, kN, kF, kHC, nullptr);
    }
    k_dots2<<<(kN * 32 + 255) / 256, 256>>>(a2s, a2d);
    k_stats2<<<(kN * 32 + 255) / 256, 256>>>();
    k_agg2<<<kN, 128>>>(b2, out);
}

// round 16
// speedup vs baseline: 1.4760x; 1.4760x over previous
#include <cuda_runtime.h>
#include <math.h>

// Problem constants (fixed by the dataset)
#define kN    20000
#define kE    320000
#define kSED  768
#define kHC   512     // heads * channels layer 1
#define kH    4
#define kHID  128
#define kF    128     // layer-2 output channels

#define NEG_INF (-3.402823466e38f)
#define TF32_MASK 0xFFFFE000u

// ---------------- scratch (no allocation allowed) ----------------
__device__ float g_h1[kN * kHC];        // layer-1 pre-bias features (messages)
__device__ float g_h1act[kN * kHC];     // after agg + b1 + ELU
__device__ float g_h2[kN * kF];         // layer-2 pre-bias features
__device__ float g_c1[kHC];             // sent @ W1[768:1536]
__device__ float g_es1[kN * kH];
__device__ float g_ed1[kN * kH];
__device__ float g_es2[kN];
__device__ float g_ed2[kN];
__device__ float g_m1[kN * kH];
__device__ float g_rs1[kN * kH];
__device__ float g_m2[kN];
__device__ float g_rs2[kN];
__device__ int   g_deg[kN];
__device__ int   g_cursor[kN];
__device__ int   g_rowptr[kN + 1];
__device__ int   g_tscan[kN];
__device__ int   g_bsum[32];
__device__ int   g_boff[32];
__device__ int   g_srcs[kE];            // src node ids sorted by dst

// ---------------- CSR build ----------------
__global__ void k_zero_deg() {
    int i = blockIdx.x * blockDim.x + threadIdx.x;
    if (i < kN) g_deg[i] = 0;
}

__global__ void k_hist(const int* __restrict__ ei) {
    int e = blockIdx.x * blockDim.x + threadIdx.x;
    if (e < kE) atomicAdd(&g_deg[ei[kE + e]], 1);
}

__global__ void k_scan1() {
    __shared__ int sm[1024];
    int i = blockIdx.x * 1024 + threadIdx.x;
    int v = (i < kN) ? g_deg[i] : 0;
    sm[threadIdx.x] = v;
    __syncthreads();
    for (int off = 1; off < 1024; off <<= 1) {
        int t = (threadIdx.x >= off) ? sm[threadIdx.x - off] : 0;
        __syncthreads();
        sm[threadIdx.x] += t;
        __syncthreads();
    }
    if (i < kN) g_tscan[i] = sm[threadIdx.x];
    if (threadIdx.x == 1023) g_bsum[blockIdx.x] = sm[1023];
}

__global__ void k_scan2(int nb) {
    if (threadIdx.x == 0) {
        int run = 0;
        for (int b = 0; b < nb; b++) { g_boff[b] = run; run += g_bsum[b]; }
    }
}

__global__ void k_scan3() {
    int i = blockIdx.x * blockDim.x + threadIdx.x;
    if (i < kN) {
        int incl = g_tscan[i] + g_boff[i >> 10];
        g_rowptr[i + 1] = incl;
        g_cursor[i]     = incl - g_deg[i];
        if (i == 0) g_rowptr[0] = 0;
    }
}

__global__ void k_scatter(const int* __restrict__ ei) {
    int e = blockIdx.x * blockDim.x + threadIdx.x;
    if (e < kE) {
        int d = ei[kE + e];
        int pos = atomicAdd(&g_cursor[d], 1);
        g_srcs[pos] = ei[e];
    }
}

// ---------------- constant column bias: c1 = sent @ W1[768:1536] ----------------
__global__ void k_c1(const float* __restrict__ sent, const float* __restrict__ W1) {
    int j = blockIdx.x * blockDim.x + threadIdx.x;   // 0..511
    if (j >= kHC) return;
    float acc = 0.f;
    for (int k = 0; k < kSED; k++)
        acc += sent[k] * W1[(kSED + k) * kHC + j];
    g_c1[j] = acc;
}

// ---------------- tf32 tensor-core GEMM, 2-term split (A hi-only, B hi+lo) ----------------
// C[M,N] = A[M,K] @ B[K,N] (+ colbias). Block 128x128, k-tile 16, 256 thr = 8 warps of 64x32.
// D = Ah*Bh + Ah*Bl  (error ~ al*b ~ 1e-4 relative, inside 1e-3 budget).
#define GBM 128
#define GBN 128
#define GBK 16
#define APAD 20
#define BPAD 136
#define OFF_AH 0
#define OFF_BH 2560           // 128*20
#define OFF_BL 4736           // 2560 + 16*136
#define BUF_FLOATS 6912       // 4736 + 16*136

__device__ __forceinline__ float tf32_hi(float x) {
    return __uint_as_float(__float_as_uint(x) & TF32_MASK);
}

__device__ __forceinline__ void mma_tf32(float* c,
    unsigned a0, unsigned a1, unsigned a2, unsigned a3,
    unsigned b0, unsigned b1)
{
    asm volatile(
        "mma.sync.aligned.m16n8k8.row.col.f32.tf32.tf32.f32 "
        "{%0,%1,%2,%3},{%4,%5,%6,%7},{%8,%9},{%0,%1,%2,%3};"
        : "+f"(c[0]), "+f"(c[1]), "+f"(c[2]), "+f"(c[3])
        : "r"(a0), "r"(a1), "r"(a2), "r"(a3), "r"(b0), "r"(b1));
}

__device__ __forceinline__ void stash_tile(
    float* buf, int aM0, int aM1, int aK, int bK0, int bK1, int bN,
    float4 va0, float4 va1, float4 vb0, float4 vb1)
{
    // A: truncate to tf32-hi only
    *(float4*)&buf[OFF_AH + aM0 * APAD + aK] = make_float4(
        tf32_hi(va0.x), tf32_hi(va0.y), tf32_hi(va0.z), tf32_hi(va0.w));
    *(float4*)&buf[OFF_AH + aM1 * APAD + aK] = make_float4(
        tf32_hi(va1.x), tf32_hi(va1.y), tf32_hi(va1.z), tf32_hi(va1.w));
    // B: hi + lo
    {
        float hx = tf32_hi(vb0.x), hy = tf32_hi(vb0.y), hz = tf32_hi(vb0.z), hw = tf32_hi(vb0.w);
        *(float4*)&buf[OFF_BH + bK0 * BPAD + bN] = make_float4(hx, hy, hz, hw);
        *(float4*)&buf[OFF_BL + bK0 * BPAD + bN] =
            make_float4(vb0.x - hx, vb0.y - hy, vb0.z - hz, vb0.w - hw);
    }
    {
        float hx = tf32_hi(vb1.x), hy = tf32_hi(vb1.y), hz = tf32_hi(vb1.z), hw = tf32_hi(vb1.w);
        *(float4*)&buf[OFF_BH + bK1 * BPAD + bN] = make_float4(hx, hy, hz, hw);
        *(float4*)&buf[OFF_BL + bK1 * BPAD + bN] =
            make_float4(vb1.x - hx, vb1.y - hy, vb1.z - hz, vb1.w - hw);
    }
}

__global__ void __launch_bounds__(256) k_mma_gemm(
    const float* __restrict__ A, const float* __restrict__ B, float* __restrict__ C,
    int M, int N, int K, const float* __restrict__ colbias)
{
    extern __shared__ float smbuf[];

    int tid  = threadIdx.x;
    int wid  = tid >> 5, lane = tid & 31;
    int g    = lane >> 2, tg = lane & 3;
    int warpM = (wid >> 2) * 64;   // 0 or 64
    int warpN = (wid & 3) * 32;    // 0,32,64,96
    int rowBase = blockIdx.y * GBM;
    int colBase = blockIdx.x * GBN;

    int aM0 = tid >> 2,          aK = (tid & 3) << 2;
    int aM1 = aM0 + 64;
    int bK0 = tid >> 5,          bN = (tid & 31) << 2;
    int bK1 = bK0 + 8;

    float acc[4][4][4];
    #pragma unroll
    for (int i = 0; i < 4; i++)
        #pragma unroll
        for (int j = 0; j < 4; j++)
            #pragma unroll
            for (int r = 0; r < 4; r++) acc[i][j][r] = 0.f;

    const float4 z4 = make_float4(0.f, 0.f, 0.f, 0.f);
    int T = K / GBK;

    // load + stash tile 0
    {
        int gm0 = rowBase + aM0, gm1 = rowBase + aM1;
        float4 va0 = (gm0 < M) ? *(const float4*)&A[(long)gm0 * K + aK] : z4;
        float4 va1 = (gm1 < M) ? *(const float4*)&A[(long)gm1 * K + aK] : z4;
        float4 vb0 = *(const float4*)&B[(long)bK0 * N + colBase + bN];
        float4 vb1 = *(const float4*)&B[(long)bK1 * N + colBase + bN];
        stash_tile(smbuf, aM0, aM1, aK, bK0, bK1, bN, va0, va1, vb0, vb1);
    }
    __syncthreads();

    for (int t = 0; t < T; t++) {
        float* cur = smbuf + (t & 1) * BUF_FLOATS;
        float* AhF = cur + OFF_AH;
        float* BhF = cur + OFF_BH;
        float* BlF = cur + OFF_BL;

        float4 pa0, pa1, pb0, pb1;
        bool more = (t + 1 < T);
        if (more) {
            int k0 = (t + 1) * GBK;
            int gm0 = rowBase + aM0, gm1 = rowBase + aM1;
            pa0 = (gm0 < M) ? *(const float4*)&A[(long)gm0 * K + k0 + aK] : z4;
            pa1 = (gm1 < M) ? *(const float4*)&A[(long)gm1 * K + k0 + aK] : z4;
            pb0 = *(const float4*)&B[(long)(k0 + bK0) * N + colBase + bN];
            pb1 = *(const float4*)&B[(long)(k0 + bK1) * N + colBase + bN];
        }

        #pragma unroll
        for (int ks = 0; ks < GBK; ks += 8) {
            unsigned ah[4][4];
            #pragma unroll
            for (int i = 0; i < 4; i++) {
                int rm = warpM + i * 16;
                ah[i][0] = __float_as_uint(AhF[(rm + g    ) * APAD + ks + tg    ]);
                ah[i][1] = __float_as_uint(AhF[(rm + g + 8) * APAD + ks + tg    ]);
                ah[i][2] = __float_as_uint(AhF[(rm + g    ) * APAD + ks + tg + 4]);
                ah[i][3] = __float_as_uint(AhF[(rm + g + 8) * APAD + ks + tg + 4]);
            }
            unsigned bh[4][2], bl[4][2];
            #pragma unroll
            for (int j = 0; j < 4; j++) {
                int cn = warpN + j * 8;
                bh[j][0] = __float_as_uint(BhF[(ks + tg    ) * BPAD + cn + g]);
                bh[j][1] = __float_as_uint(BhF[(ks + tg + 4) * BPAD + cn + g]);
                bl[j][0] = __float_as_uint(BlF[(ks + tg    ) * BPAD + cn + g]);
                bl[j][1] = __float_as_uint(BlF[(ks + tg + 4) * BPAD + cn + g]);
            }
            #pragma unroll
            for (int i = 0; i < 4; i++)
                #pragma unroll
                for (int j = 0; j < 4; j++) {
                    mma_tf32(acc[i][j], ah[i][0], ah[i][1], ah[i][2], ah[i][3], bh[j][0], bh[j][1]);
                    mma_tf32(acc[i][j], ah[i][0], ah[i][1], ah[i][2], ah[i][3], bl[j][0], bl[j][1]);
                }
        }

        if (more) {
            float* nxt = smbuf + ((t + 1) & 1) * BUF_FLOATS;
            stash_tile(nxt, aM0, aM1, aK, bK0, bK1, bN, pa0, pa1, pb0, pb1);
            __syncthreads();
        }
    }

    // epilogue
    #pragma unroll
    for (int i = 0; i < 4; i++) {
        int r0 = rowBase + warpM + i * 16 + g;
        int r1 = r0 + 8;
        #pragma unroll
        for (int j = 0; j < 4; j++) {
            int c = colBase + warpN + j * 8 + tg * 2;
            float2 v0 = make_float2(acc[i][j][0], acc[i][j][1]);
            float2 v1 = make_float2(acc[i][j][2], acc[i][j][3]);
            if (colbias) {
                float cb0 = colbias[c], cb1 = colbias[c + 1];
                v0.x += cb0; v0.y += cb1;
                v1.x += cb0; v1.y += cb1;
            }
            if (r0 < M) *(float2*)&C[(long)r0 * N + c] = v0;
            if (r1 < M) *(float2*)&C[(long)r1 * N + c] = v1;
        }
    }
}

// ---------------- attention scalar dots ----------------
__global__ void k_dots1(const float* __restrict__ a_src, const float* __restrict__ a_dst) {
    int gw = (blockIdx.x * blockDim.x + threadIdx.x) >> 5;
    int lane = threadIdx.x & 31;
    if (gw >= kN * kH) return;
    int n = gw >> 2, h = gw & 3;
    const float* row = g_h1 + (long)n * kHC + h * kHID;
    const float* as = a_src + h * kHID;
    const float* ad = a_dst + h * kHID;
    float s1 = 0.f, s2 = 0.f;
    #pragma unroll
    for (int c = lane; c < kHID; c += 32) {
        float v = row[c];
        s1 += v * as[c];
        s2 += v * ad[c];
    }
    #pragma unroll
    for (int o = 16; o; o >>= 1) {
        s1 += __shfl_xor_sync(0xffffffffu, s1, o);
        s2 += __shfl_xor_sync(0xffffffffu, s2, o);
    }
    if (lane == 0) { g_es1[gw] = s1; g_ed1[gw] = s2; }
}

__global__ void k_dots2(const float* __restrict__ a_src, const float* __restrict__ a_dst) {
    int gw = (blockIdx.x * blockDim.x + threadIdx.x) >> 5;
    int lane = threadIdx.x & 31;
    if (gw >= kN) return;
    const float* row = g_h2 + (long)gw * kF;
    float s1 = 0.f, s2 = 0.f;
    #pragma unroll
    for (int c = lane; c < kF; c += 32) {
        float v = row[c];
        s1 += v * a_src[c];
        s2 += v * a_dst[c];
    }
    #pragma unroll
    for (int o = 16; o; o >>= 1) {
        s1 += __shfl_xor_sync(0xffffffffu, s1, o);
        s2 += __shfl_xor_sync(0xffffffffu, s2, o);
    }
    if (lane == 0) { g_es2[gw] = s1; g_ed2[gw] = s2; }
}

// ---------------- warp-per-node softmax stats ----------------
__global__ void k_stats1() {
    int gw = (blockIdx.x * blockDim.x + threadIdx.x) >> 5;   // node
    int lane = threadIdx.x & 31;
    if (gw >= kN) return;
    int beg = g_rowptr[gw], end = g_rowptr[gw + 1];
    float4 ed = *(const float4*)&g_ed1[gw * 4];

    float m0 = NEG_INF, m1 = NEG_INF, m2 = NEG_INF, m3 = NEG_INF;
    for (int j = beg + lane; j < end; j += 32) {
        int s = g_srcs[j];
        float4 es = *(const float4*)&g_es1[s * 4];
        float e0 = es.x + ed.x; e0 = e0 > 0.f ? e0 : 0.2f * e0;
        float e1 = es.y + ed.y; e1 = e1 > 0.f ? e1 : 0.2f * e1;
        float e2 = es.z + ed.z; e2 = e2 > 0.f ? e2 : 0.2f * e2;
        float e3 = es.w + ed.w; e3 = e3 > 0.f ? e3 : 0.2f * e3;
        m0 = fmaxf(m0, e0); m1 = fmaxf(m1, e1);
        m2 = fmaxf(m2, e2); m3 = fmaxf(m3, e3);
    }
    #pragma unroll
    for (int o = 16; o; o >>= 1) {
        m0 = fmaxf(m0, __shfl_xor_sync(0xffffffffu, m0, o));
        m1 = fmaxf(m1, __shfl_xor_sync(0xffffffffu, m1, o));
        m2 = fmaxf(m2, __shfl_xor_sync(0xffffffffu, m2, o));
        m3 = fmaxf(m3, __shfl_xor_sync(0xffffffffu, m3, o));
    }
    float s0 = 0.f, s1 = 0.f, s2 = 0.f, s3 = 0.f;
    for (int j = beg + lane; j < end; j += 32) {
        int s = g_srcs[j];
        float4 es = *(const float4*)&g_es1[s * 4];
        float e0 = es.x + ed.x; e0 = e0 > 0.f ? e0 : 0.2f * e0;
        float e1 = es.y + ed.y; e1 = e1 > 0.f ? e1 : 0.2f * e1;
        float e2 = es.z + ed.z; e2 = e2 > 0.f ? e2 : 0.2f * e2;
        float e3 = es.w + ed.w; e3 = e3 > 0.f ? e3 : 0.2f * e3;
        s0 += __expf(e0 - m0); s1 += __expf(e1 - m1);
        s2 += __expf(e2 - m2); s3 += __expf(e3 - m3);
    }
    #pragma unroll
    for (int o = 16; o; o >>= 1) {
        s0 += __shfl_xor_sync(0xffffffffu, s0, o);
        s1 += __shfl_xor_sync(0xffffffffu, s1, o);
        s2 += __shfl_xor_sync(0xffffffffu, s2, o);
        s3 += __shfl_xor_sync(0xffffffffu, s3, o);
    }
    if (lane == 0) {
        *(float4*)&g_m1[gw * 4]  = make_float4(m0, m1, m2, m3);
        *(float4*)&g_rs1[gw * 4] = make_float4(1.f / (s0 + 1e-16f), 1.f / (s1 + 1e-16f),
                                               1.f / (s2 + 1e-16f), 1.f / (s3 + 1e-16f));
    }
}

__global__ void k_stats2() {
    int gw = (blockIdx.x * blockDim.x + threadIdx.x) >> 5;
    int lane = threadIdx.x & 31;
    if (gw >= kN) return;
    int beg = g_rowptr[gw], end = g_rowptr[gw + 1];
    float ed = g_ed2[gw];
    float m = NEG_INF;
    for (int j = beg + lane; j < end; j += 32) {
        float e = g_es2[g_srcs[j]] + ed;
        e = e > 0.f ? e : 0.2f * e;
        m = fmaxf(m, e);
    }
    #pragma unroll
    for (int o = 16; o; o >>= 1) m = fmaxf(m, __shfl_xor_sync(0xffffffffu, m, o));
    float s = 0.f;
    for (int j = beg + lane; j < end; j += 32) {
        float e = g_es2[g_srcs[j]] + ed;
        e = e > 0.f ? e : 0.2f * e;
        s += __expf(e - m);
    }
    #pragma unroll
    for (int o = 16; o; o >>= 1) s += __shfl_xor_sync(0xffffffffu, s, o);
    if (lane == 0) { g_m2[gw] = m; g_rs2[gw] = 1.f / (s + 1e-16f); }
}

// ---------------- layer-1 aggregation: gather only, +b1, ELU ----------------
__global__ void __launch_bounds__(512) k_agg1(const float* __restrict__ b1) {
    __shared__ float msm[4], rssm[4], edsm[4];
    __shared__ float alpha_sm[128 * 4];
    __shared__ int   src_sm[128];

    int v = blockIdx.x;
    int tid = threadIdx.x;
    int beg = g_rowptr[v], end = g_rowptr[v + 1];
    int h = tid >> 7;

    if (tid < 4) {
        msm[tid]  = g_m1[v * 4 + tid];
        rssm[tid] = g_rs1[v * 4 + tid];
        edsm[tid] = g_ed1[v * 4 + tid];
    }
    __syncthreads();

    float acc0 = 0.f, acc1 = 0.f, acc2 = 0.f, acc3 = 0.f;
    for (int cb = beg; cb < end; cb += 128) {
        int cn = min(128, end - cb);
        for (int idx = tid; idx < cn * 4; idx += 512) {
            int j = idx >> 2, hh = idx & 3;
            int s = g_srcs[cb + j];
            float e = g_es1[s * 4 + hh] + edsm[hh];
            e = e > 0.f ? e : 0.2f * e;
            alpha_sm[(j << 2) + hh] = __expf(e - msm[hh]) * rssm[hh];
            if (hh == 0) src_sm[j] = s;
        }
        __syncthreads();
        int j = 0;
        for (; j + 4 <= cn; j += 4) {
            float a0 = alpha_sm[(j << 2) + h];
            float a1 = alpha_sm[((j + 1) << 2) + h];
            float a2 = alpha_sm[((j + 2) << 2) + h];
            float a3 = alpha_sm[((j + 3) << 2) + h];
            int s0 = src_sm[j], s1 = src_sm[j + 1], s2 = src_sm[j + 2], s3 = src_sm[j + 3];
            acc0 += a0 * g_h1[(long)s0 * kHC + tid];
            acc1 += a1 * g_h1[(long)s1 * kHC + tid];
            acc2 += a2 * g_h1[(long)s2 * kHC + tid];
            acc3 += a3 * g_h1[(long)s3 * kHC + tid];
        }
        for (; j < cn; j++)
            acc0 += alpha_sm[(j << 2) + h] * g_h1[(long)src_sm[j] * kHC + tid];
        __syncthreads();
    }
    float o = acc0 + acc1 + acc2 + acc3 + b1[tid];
    g_h1act[(long)v * kHC + tid] = o > 0.f ? o : (__expf(o) - 1.f);   // ELU(alpha=1)
}

// ---------------- layer-2 aggregation (single head), +b2, write out ----------------
__global__ void __launch_bounds__(128) k_agg2(const float* __restrict__ b2, float* __restrict__ out) {
    __shared__ float alpha_sm[256];
    __shared__ int   src_sm[256];

    int v = blockIdx.x;
    int tid = threadIdx.x;
    int beg = g_rowptr[v], end = g_rowptr[v + 1];
    float edv = g_ed2[v];
    float m = g_m2[v];
    float rs = g_rs2[v];

    float acc0 = 0.f, acc1 = 0.f, acc2 = 0.f, acc3 = 0.f;
    for (int cb = beg; cb < end; cb += 256) {
        int cn = min(256, end - cb);
        for (int idx = tid; idx < cn; idx += 128) {
            int s = g_srcs[cb + idx];
            float e = g_es2[s] + edv;
            e = e > 0.f ? e : 0.2f * e;
            alpha_sm[idx] = __expf(e - m) * rs;
            src_sm[idx] = s;
        }
        __syncthreads();
        int j = 0;
        for (; j + 4 <= cn; j += 4) {
            float a0 = alpha_sm[j], a1 = alpha_sm[j + 1], a2 = alpha_sm[j + 2], a3 = alpha_sm[j + 3];
            int s0 = src_sm[j], s1 = src_sm[j + 1], s2 = src_sm[j + 2], s3 = src_sm[j + 3];
            acc0 += a0 * g_h2[(long)s0 * kF + tid];
            acc1 += a1 * g_h2[(long)s1 * kF + tid];
            acc2 += a2 * g_h2[(long)s2 * kF + tid];
            acc3 += a3 * g_h2[(long)s3 * kF + tid];
        }
        for (; j < cn; j++)
            acc0 += alpha_sm[j] * g_h2[(long)src_sm[j] * kF + tid];
        __syncthreads();
    }
    out[(long)v * kF + tid] = acc0 + acc1 + acc2 + acc3 + b2[tid];
}

// ---------------- launch ----------------
extern "C" void kernel_launch(void* const* d_in, const int* in_sizes, int n_in,
                              void* d_out, int out_size) {
    const float* x    = (const float*)d_in[0];
    const int*   ei   = (const int*)d_in[1];
    const float* sent = (const float*)d_in[2];
    const float* W1   = (const float*)d_in[3];
    const float* a1s  = (const float*)d_in[4];
    const float* a1d  = (const float*)d_in[5];
    const float* b1   = (const float*)d_in[6];
    const float* W2   = (const float*)d_in[7];
    const float* a2s  = (const float*)d_in[8];
    const float* a2d  = (const float*)d_in[9];
    const float* b2   = (const float*)d_in[10];
    float* out = (float*)d_out;

    const int dynsmem = BUF_FLOATS * 2 * (int)sizeof(float);   // 55296 B
    cudaFuncSetAttribute(k_mma_gemm, cudaFuncAttributeMaxDynamicSharedMemorySize, dynsmem);

    float *c1p, *h1p, *h1ap, *h2p;
    cudaGetSymbolAddress((void**)&c1p,  g_c1);
    cudaGetSymbolAddress((void**)&h1p,  g_h1);
    cudaGetSymbolAddress((void**)&h1ap, g_h1act);
    cudaGetSymbolAddress((void**)&h2p,  g_h2);

    // Launch order arranged so k_mma_gemm (GEMM1) is launch index 3 — the one ncu profiles.
    k_c1<<<2, 256>>>(sent, W1);                                  // 0
    k_zero_deg<<<(kN + 255) / 256, 256>>>();                     // 1
    k_hist<<<(kE + 255) / 256, 256>>>(ei);                       // 2
    {
        dim3 g(kHC / 128, (kN + 127) / 128);
        k_mma_gemm<<<g, 256, dynsmem>>>(x, W1, h1p, kN, kHC, kSED, c1p);   // 3  <-- profiled
    }
    k_scan1<<<(kN + 1023) / 1024, 1024>>>();                     // 4
    k_scan2<<<1, 32>>>((kN + 1023) / 1024);                      // 5
    k_scan3<<<(kN + 255) / 256, 256>>>();                        // 6
    k_scatter<<<(kE + 255) / 256, 256>>>(ei);                    // 7

    k_dots1<<<(kN * kH * 32 + 255) / 256, 256>>>(a1s, a1d);
    k_stats1<<<(kN * 32 + 255) / 256, 256>>>();
    k_agg1<<<kN, 512>>>(b1);

    {
        dim3 g(kF / 128, (kN + 127) / 128);
        k_mma_gemm<<<g, 256, dynsmem>>>(h1ap, W2, h2p, kN, kF, kHC, nullptr);
    }
    k_dots2<<<(kN * 32 + 255) / 256, 256>>>(a2s, a2d);
    k_stats2<<<(kN * 32 + 255) / 256, 256>>>();
    k_agg2<<<kN, 128>>>(b2, out);
}